// round 3
// baseline (speedup 1.0000x reference)
#include <cuda_runtime.h>

// Pool_26517128085982: 2x2 mean pool, stride 2, x:(16,64,512,512) f32 -> (16,64,256,256) f32
// Treated as 1024 independent 512x512 images -> 256x256 outputs.
// Each thread: 1 float4 output (4 out pixels) <- 4 float4 input loads (2 per source row).
// Pure HBM-streaming kernel; 2.68 GB total traffic, expect ~400-460 us on GB300.

static constexpr int W_IN   = 512;
static constexpr int W_OUT  = 256;
static constexpr int H_OUT  = 256;
static constexpr int ROW4_IN  = W_IN / 4;    // 128 float4 per input row
static constexpr int ROW4_OUT = W_OUT / 4;   // 64 float4 per output row
static constexpr int IMG4_IN  = W_IN * W_IN / 4;  // 65536 float4 per input image

__global__ __launch_bounds__(256) void Pool_26517128085982_kernel(
    const float4* __restrict__ in,
    const float*  __restrict__ kern,   // 4 floats: k00 k01 k10 k11
    float4* __restrict__ out,
    int n_out4)
{
    int idx = blockIdx.x * blockDim.x + threadIdx.x;
    if (idx >= n_out4) return;

    // idx -> (img, oh, oc4): 64 float4 per out row, 256 rows per image
    int oc4 = idx & (ROW4_OUT - 1);          // 0..63
    int oh  = (idx >> 6) & (H_OUT - 1);      // 0..255
    int img = idx >> 14;                     // 0..1023

    // input base: row 2*oh, col 8*oc4  (in float4 units)
    int base = img * IMG4_IN + (oh << 1) * ROW4_IN + (oc4 << 1);

    // 4 independent 128-bit loads (MLP=4)
    float4 a0 = in[base];
    float4 a1 = in[base + 1];
    float4 b0 = in[base + ROW4_IN];
    float4 b1 = in[base + ROW4_IN + 1];

    // kernel weights: 1 vector load, L1/L2-hit for everyone
    float4 k = *reinterpret_cast<const float4*>(kern);

    float4 o;
    o.x = k.x * a0.x + k.y * a0.y + k.z * b0.x + k.w * b0.y;
    o.y = k.x * a0.z + k.y * a0.w + k.z * b0.z + k.w * b0.w;
    o.z = k.x * a1.x + k.y * a1.y + k.z * b1.x + k.w * b1.y;
    o.w = k.x * a1.z + k.y * a1.w + k.z * b1.z + k.w * b1.w;

    out[idx] = o;
}

extern "C" void kernel_launch(void* const* d_in, const int* in_sizes, int n_in,
                              void* d_out, int out_size)
{
    const float4* x    = (const float4*)d_in[0];
    const float*  kern = (const float*)d_in[1];
    float4*       out  = (float4*)d_out;

    int n_out4 = out_size / 4;               // 16,777,216 float4
    int blocks = (n_out4 + 255) / 256;       // 65,536 blocks
    Pool_26517128085982_kernel<<<blocks, 256>>>(x, kern, out, n_out4);
}